// round 3
// baseline (speedup 1.0000x reference)
#include <cuda_runtime.h>
#include <cstdint>
#include <cstddef>

#define N_NODES 50000
#define N_EDGES 1600000
#define IN_F 256
#define OUT_F 128
#define ALPHA 0.2f
#define EPS_V 1e-9f
#define NCHUNK ((N_NODES + 255) / 256)   // 196

// ---------------- static device scratch (no allocations allowed) ----------------
__device__ int   g_src[N_EDGES];
__device__ int   g_dst[N_EDGES];
__device__ int   g_edst[N_EDGES];        // CSR: dst indices grouped by src
__device__ int   g_deg[N_NODES];
__device__ int   g_fill[N_NODES];
__device__ int   g_rowptr[N_NODES];
__device__ int   g_csum[NCHUNK];
__device__ int   g_coff[NCHUNK];
__device__ float g_h[(size_t)N_NODES * OUT_F];   // h = x @ W
__device__ float g_ssrc[N_NODES];                // h[n] . a[0:128]
__device__ float g_sdst[N_NODES];                // h[n] . a[128:256]

// ---------------- packed f32x2 helpers (sm_103a) --------------------------------
__device__ __forceinline__ unsigned long long pack2(float lo, float hi) {
    unsigned long long r;
    asm("mov.b64 %0, {%1, %2};" : "=l"(r) : "f"(lo), "f"(hi));
    return r;
}
__device__ __forceinline__ void unpack2(unsigned long long p, float& lo, float& hi) {
    asm("mov.b64 {%0, %1}, %2;" : "=f"(lo), "=f"(hi) : "l"(p));
}
__device__ __forceinline__ unsigned long long fma2(unsigned long long a,
                                                   unsigned long long b,
                                                   unsigned long long c) {
    unsigned long long d;
    asm("fma.rn.f32x2 %0, %1, %2, %3;" : "=l"(d) : "l"(a), "l"(b), "l"(c));
    return d;
}

// ---------------- zero counters (must run every launch — graph replays) ---------
__global__ void zero_counts_kernel() {
    int idx = blockIdx.x * blockDim.x + threadIdx.x;
    int stride = gridDim.x * blockDim.x;
    for (int i = idx; i < N_NODES; i += stride) {
        g_deg[i] = 0;
        g_fill[i] = 0;
    }
}

// ------ edge index normalization (int32 or int64 input) + degree histogram ------
__global__ void convert_edges_kernel(const void* __restrict__ ei) {
    const int* p32 = (const int*)ei;
    // Detect int64: values < 2^31 (nonneg) so every high 32-bit word is 0.
    bool is64 = true;
    #pragma unroll
    for (int i = 0; i < 32; i++) {
        if (p32[2 * i + 1] != 0) { is64 = false; break; }
    }
    int idx = blockIdx.x * blockDim.x + threadIdx.x;
    int stride = gridDim.x * blockDim.x;
    if (is64) {
        const long long* p64 = (const long long*)ei;
        for (int i = idx; i < N_EDGES; i += stride) {
            int s = (int)p64[i];
            int d = (int)p64[N_EDGES + i];
            g_src[i] = s;
            g_dst[i] = d;
            atomicAdd(&g_deg[s], 1);
        }
    } else {
        for (int i = idx; i < N_EDGES; i += stride) {
            int s = p32[i];
            int d = p32[N_EDGES + i];
            g_src[i] = s;
            g_dst[i] = d;
            atomicAdd(&g_deg[s], 1);
        }
    }
}

// ---------------- 2-level exclusive scan of g_deg -> g_rowptr -------------------
__global__ __launch_bounds__(256) void deg_chunk_sum_kernel() {
    __shared__ int sh[256];
    int i = blockIdx.x * 256 + threadIdx.x;
    int v = (i < N_NODES) ? g_deg[i] : 0;
    sh[threadIdx.x] = v;
    __syncthreads();
    #pragma unroll
    for (int s = 128; s > 0; s >>= 1) {
        if (threadIdx.x < s) sh[threadIdx.x] += sh[threadIdx.x + s];
        __syncthreads();
    }
    if (threadIdx.x == 0) g_csum[blockIdx.x] = sh[0];
}

__global__ __launch_bounds__(256) void scan_chunk_sums_kernel() {
    __shared__ int sh[256];
    int t = threadIdx.x;
    int v = (t < NCHUNK) ? g_csum[t] : 0;
    sh[t] = v;
    __syncthreads();
    #pragma unroll
    for (int off = 1; off < 256; off <<= 1) {
        int x = (t >= off) ? sh[t - off] : 0;
        __syncthreads();
        sh[t] += x;
        __syncthreads();
    }
    if (t < NCHUNK) g_coff[t] = sh[t] - v;   // exclusive
}

__global__ __launch_bounds__(256) void rowptr_kernel() {
    __shared__ int sh[256];
    int t = threadIdx.x;
    int i = blockIdx.x * 256 + t;
    int v = (i < N_NODES) ? g_deg[i] : 0;
    sh[t] = v;
    __syncthreads();
    #pragma unroll
    for (int off = 1; off < 256; off <<= 1) {
        int x = (t >= off) ? sh[t - off] : 0;
        __syncthreads();
        sh[t] += x;
        __syncthreads();
    }
    if (i < N_NODES) g_rowptr[i] = g_coff[blockIdx.x] + sh[t] - v;
}

// ---------------- CSR fill: group dst by src ------------------------------------
__global__ void csr_fill_kernel() {
    int idx = blockIdx.x * blockDim.x + threadIdx.x;
    int stride = gridDim.x * blockDim.x;
    for (int i = idx; i < N_EDGES; i += stride) {
        int s = g_src[i];
        int ofs = atomicAdd(&g_fill[s], 1);
        g_edst[g_rowptr[s] + ofs] = g_dst[i];
    }
}

// ------ GEMM: h = x @ W  (fp32, FFMA2 packed), fused per-node score epilogue ----
#define GB_M 64
#define GB_K 16
__global__ __launch_bounds__(256) void gemm_kernel(const float* __restrict__ x,
                                                   const float* __restrict__ W,
                                                   const float* __restrict__ a) {
    __shared__ __align__(16) float As[GB_K][GB_M + 4];   // x tile, transposed
    __shared__ __align__(16) float Ws[GB_K][OUT_F];
    const int block_row = blockIdx.x * GB_M;
    const int tid = threadIdx.x;                   // 256 threads
    const int ty = tid >> 5;                       // warp id 0..7 -> rows ty*8..+7
    const int tx = tid & 31;                       // lane -> cols tx*4..+3

    const int lrow = tid >> 2;                     // 0..63
    const int lk4  = (tid & 3) * 4;                // 0,4,8,12

    unsigned long long acc2[4][4];
    #pragma unroll
    for (int i = 0; i < 4; i++)
        #pragma unroll
        for (int j = 0; j < 4; j++) acc2[i][j] = 0ULL;

    for (int k0 = 0; k0 < IN_F; k0 += GB_K) {
        float4 xv = make_float4(0.f, 0.f, 0.f, 0.f);
        int grow = block_row + lrow;
        if (grow < N_NODES)
            xv = *(const float4*)(x + (size_t)grow * IN_F + k0 + lk4);
        As[lk4 + 0][lrow] = xv.x;
        As[lk4 + 1][lrow] = xv.y;
        As[lk4 + 2][lrow] = xv.z;
        As[lk4 + 3][lrow] = xv.w;
        #pragma unroll
        for (int i = 0; i < 2; i++) {
            int fi = tid + i * 256;
            int wk = fi >> 5;
            int wn = (fi & 31) * 4;
            *(float4*)&Ws[wk][wn] =
                *(const float4*)(W + (size_t)(k0 + wk) * OUT_F + wn);
        }
        __syncthreads();
        #pragma unroll
        for (int k = 0; k < GB_K; k++) {
            float4 rnv = *(const float4*)&Ws[k][tx * 4];
            unsigned long long rnd[4] = {
                pack2(rnv.x, rnv.x), pack2(rnv.y, rnv.y),
                pack2(rnv.z, rnv.z), pack2(rnv.w, rnv.w)
            };
            #pragma unroll
            for (int i = 0; i < 4; i++) {
                unsigned long long rm =
                    *(const unsigned long long*)&As[k][ty * 8 + 2 * i];
                #pragma unroll
                for (int j = 0; j < 4; j++)
                    acc2[i][j] = fma2(rm, rnd[j], acc2[i][j]);
            }
        }
        __syncthreads();
    }

    float accf[8][4];
    #pragma unroll
    for (int i = 0; i < 4; i++)
        #pragma unroll
        for (int j = 0; j < 4; j++)
            unpack2(acc2[i][j], accf[2 * i][j], accf[2 * i + 1][j]);

    float4 as4 = ((const float4*)a)[tx];
    float4 ad4 = ((const float4*)(a + OUT_F))[tx];
    #pragma unroll
    for (int r = 0; r < 8; r++) {
        int grow = block_row + ty * 8 + r;
        if (grow < N_NODES) {
            float4 v = make_float4(accf[r][0], accf[r][1], accf[r][2], accf[r][3]);
            *(float4*)(g_h + (size_t)grow * OUT_F + tx * 4) = v;
            float s1 = v.x * as4.x + v.y * as4.y + v.z * as4.z + v.w * as4.w;
            float s2 = v.x * ad4.x + v.y * ad4.y + v.z * ad4.z + v.w * ad4.w;
            #pragma unroll
            for (int o = 16; o > 0; o >>= 1) {
                s1 += __shfl_xor_sync(0xFFFFFFFFu, s1, o);
                s2 += __shfl_xor_sync(0xFFFFFFFFu, s2, o);
            }
            if (tx == 0) {
                g_ssrc[grow] = s1;
                g_sdst[grow] = s2;
            }
        }
    }
}

// ---- aggregate: one warp per node; rowsum in registers; fused divide + ELU -----
__global__ __launch_bounds__(256) void aggregate_kernel(float* __restrict__ out) {
    int node = (blockIdx.x * blockDim.x + threadIdx.x) >> 5;
    int lane = threadIdx.x & 31;
    if (node >= N_NODES) return;

    int beg = g_rowptr[node];
    int end = beg + g_deg[node];
    float ss = g_ssrc[node];

    float ax = 0.f, ay = 0.f, az = 0.f, aw = 0.f;
    float rowsum = 0.f;

    int e = beg;
    for (; e + 1 < end; e += 2) {
        int d0 = g_edst[e];
        int d1 = g_edst[e + 1];
        float4 h0 = ((const float4*)(g_h + (size_t)d0 * OUT_F))[lane];
        float4 h1 = ((const float4*)(g_h + (size_t)d1 * OUT_F))[lane];
        float sc0 = ss + g_sdst[d0];
        float sc1 = ss + g_sdst[d1];
        float lr0 = sc0 > 0.f ? sc0 : ALPHA * sc0;
        float lr1 = sc1 > 0.f ? sc1 : ALPHA * sc1;
        float w0 = __expf(-lr0);
        float w1 = __expf(-lr1);
        rowsum += w0 + w1;
        ax += w0 * h0.x + w1 * h1.x;
        ay += w0 * h0.y + w1 * h1.y;
        az += w0 * h0.z + w1 * h1.z;
        aw += w0 * h0.w + w1 * h1.w;
    }
    if (e < end) {
        int d0 = g_edst[e];
        float4 h0 = ((const float4*)(g_h + (size_t)d0 * OUT_F))[lane];
        float sc0 = ss + g_sdst[d0];
        float lr0 = sc0 > 0.f ? sc0 : ALPHA * sc0;
        float w0 = __expf(-lr0);
        rowsum += w0;
        ax += w0 * h0.x;
        ay += w0 * h0.y;
        az += w0 * h0.z;
        aw += w0 * h0.w;
    }

    float inv = 1.0f / (rowsum + EPS_V);
    float hx = ax * inv, hy = ay * inv, hz = az * inv, hw = aw * inv;
    float4 r;
    r.x = hx > 0.f ? hx : (__expf(hx) - 1.0f);
    r.y = hy > 0.f ? hy : (__expf(hy) - 1.0f);
    r.z = hz > 0.f ? hz : (__expf(hz) - 1.0f);
    r.w = hw > 0.f ? hw : (__expf(hw) - 1.0f);
    ((float4*)(out + (size_t)node * OUT_F))[lane] = r;
}

// ---------------- launch --------------------------------------------------------
extern "C" void kernel_launch(void* const* d_in, const int* in_sizes, int n_in,
                              void* d_out, int out_size) {
    const float* x  = (const float*)d_in[0];
    const void*  ei = d_in[1];
    const float* W  = (const float*)d_in[2];
    const float* a  = (const float*)d_in[3];
    float* out = (float*)d_out;

    zero_counts_kernel<<<256, 256>>>();
    convert_edges_kernel<<<2048, 256>>>(ei);

    int gemm_blocks = (N_NODES + GB_M - 1) / GB_M;        // 782
    gemm_kernel<<<gemm_blocks, 256>>>(x, W, a);

    deg_chunk_sum_kernel<<<NCHUNK, 256>>>();
    scan_chunk_sums_kernel<<<1, 256>>>();
    rowptr_kernel<<<NCHUNK, 256>>>();
    csr_fill_kernel<<<2048, 256>>>();

    int agg_blocks = (N_NODES * 32 + 255) / 256;          // 6250
    aggregate_kernel<<<agg_blocks, 256>>>(out);
}

// round 11
// speedup vs baseline: 1.1417x; 1.1417x over previous
#include <cuda_runtime.h>
#include <cuda_fp16.h>
#include <cstdint>
#include <cstddef>

#define N_NODES 50000
#define N_EDGES 1600000
#define IN_F 256
#define OUT_F 128
#define ALPHA 0.2f
#define EPS_V 1e-9f
#define NCHUNK ((N_NODES + 255) / 256)   // 196

// ---------------- static device scratch (no allocations allowed) ----------------
__device__ int    g_edst[N_EDGES];        // CSR: dst indices grouped by src
__device__ int    g_deg[N_NODES];
__device__ int    g_fill[N_NODES];
__device__ int    g_rowptr[N_NODES];
__device__ int    g_csum[NCHUNK];
__device__ int    g_coff[NCHUNK];
__device__ __half g_hh[(size_t)N_NODES * OUT_F];  // h = x @ W, fp16 payload
__device__ float  g_ssrc[N_NODES];                // h[n] . a[0:128]  (fp32)
__device__ float  g_sdst[N_NODES];                // h[n] . a[128:256] (fp32)

// ---------------- packed f32x2 helpers (sm_103a) --------------------------------
__device__ __forceinline__ unsigned long long pack2(float lo, float hi) {
    unsigned long long r;
    asm("mov.b64 %0, {%1, %2};" : "=l"(r) : "f"(lo), "f"(hi));
    return r;
}
__device__ __forceinline__ void unpack2(unsigned long long p, float& lo, float& hi) {
    asm("mov.b64 {%0, %1}, %2;" : "=f"(lo), "=f"(hi) : "l"(p));
}
__device__ __forceinline__ unsigned long long fma2(unsigned long long a,
                                                   unsigned long long b,
                                                   unsigned long long c) {
    unsigned long long d;
    asm("fma.rn.f32x2 %0, %1, %2, %3;" : "=l"(d) : "l"(a), "l"(b), "l"(c));
    return d;
}

// int64-vs-int32 edge_index sniff (values < 2^31 -> all high words zero if i64)
__device__ __forceinline__ bool edges_are_i64(const void* ei) {
    const int* p32 = (const int*)ei;
    #pragma unroll
    for (int i = 0; i < 32; i++)
        if (p32[2 * i + 1] != 0) return false;
    return true;
}

// ---------------- zero counters (graph replays -> must re-zero each launch) -----
__global__ void zero_counts_kernel() {
    int idx = blockIdx.x * blockDim.x + threadIdx.x;
    int stride = gridDim.x * blockDim.x;
    for (int i = idx; i < N_NODES; i += stride) {
        g_deg[i] = 0;
        g_fill[i] = 0;
    }
}

// ---------------- degree histogram straight off edge_index ----------------------
__global__ void hist_kernel(const void* __restrict__ ei) {
    bool is64 = edges_are_i64(ei);
    int idx = blockIdx.x * blockDim.x + threadIdx.x;
    int stride = gridDim.x * blockDim.x;
    if (is64) {
        const long long* p64 = (const long long*)ei;
        for (int i = idx; i < N_EDGES; i += stride)
            atomicAdd(&g_deg[(int)p64[i]], 1);
    } else {
        const int* p32 = (const int*)ei;
        for (int i = idx; i < N_EDGES; i += stride)
            atomicAdd(&g_deg[p32[i]], 1);
    }
}

// ---------------- 2-level exclusive scan of g_deg -> g_rowptr -------------------
__global__ __launch_bounds__(256) void deg_chunk_sum_kernel() {
    __shared__ int sh[256];
    int i = blockIdx.x * 256 + threadIdx.x;
    int v = (i < N_NODES) ? g_deg[i] : 0;
    sh[threadIdx.x] = v;
    __syncthreads();
    #pragma unroll
    for (int s = 128; s > 0; s >>= 1) {
        if (threadIdx.x < s) sh[threadIdx.x] += sh[threadIdx.x + s];
        __syncthreads();
    }
    if (threadIdx.x == 0) g_csum[blockIdx.x] = sh[0];
}

__global__ __launch_bounds__(256) void scan_chunk_sums_kernel() {
    __shared__ int sh[256];
    int t = threadIdx.x;
    int v = (t < NCHUNK) ? g_csum[t] : 0;
    sh[t] = v;
    __syncthreads();
    #pragma unroll
    for (int off = 1; off < 256; off <<= 1) {
        int x = (t >= off) ? sh[t - off] : 0;
        __syncthreads();
        sh[t] += x;
        __syncthreads();
    }
    if (t < NCHUNK) g_coff[t] = sh[t] - v;   // exclusive
}

__global__ __launch_bounds__(256) void rowptr_kernel() {
    __shared__ int sh[256];
    int t = threadIdx.x;
    int i = blockIdx.x * 256 + t;
    int v = (i < N_NODES) ? g_deg[i] : 0;
    sh[t] = v;
    __syncthreads();
    #pragma unroll
    for (int off = 1; off < 256; off <<= 1) {
        int x = (t >= off) ? sh[t - off] : 0;
        __syncthreads();
        sh[t] += x;
        __syncthreads();
    }
    if (i < N_NODES) g_rowptr[i] = g_coff[blockIdx.x] + sh[t] - v;
}

// ===== fused kernel: blocks [0, GEMM_BLOCKS) do GEMM; the rest do CSR fill ======
#define GB_M 64
#define GB_K 16
#define GEMM_BLOCKS ((N_NODES + GB_M - 1) / GB_M)   // 782
#define FILL_BLOCKS 512

__global__ __launch_bounds__(256) void gemm_fill_kernel(const float* __restrict__ x,
                                                        const float* __restrict__ W,
                                                        const float* __restrict__ a,
                                                        const void* __restrict__ ei) {
    if (blockIdx.x >= GEMM_BLOCKS) {
        // ---------------- CSR fill path (independent of GEMM) -------------------
        int idx = (blockIdx.x - GEMM_BLOCKS) * blockDim.x + threadIdx.x;
        int stride = FILL_BLOCKS * blockDim.x;
        if (edges_are_i64(ei)) {
            const long long* p64 = (const long long*)ei;
            for (int i = idx; i < N_EDGES; i += stride) {
                int s = (int)p64[i];
                int d = (int)p64[N_EDGES + i];
                int ofs = atomicAdd(&g_fill[s], 1);
                g_edst[g_rowptr[s] + ofs] = d;
            }
        } else {
            const int* p32 = (const int*)ei;
            for (int i = idx; i < N_EDGES; i += stride) {
                int s = p32[i];
                int d = p32[N_EDGES + i];
                int ofs = atomicAdd(&g_fill[s], 1);
                g_edst[g_rowptr[s] + ofs] = d;
            }
        }
        return;
    }

    // ---------------- GEMM path: h = x @ W (FFMA2), fused score epilogue --------
    __shared__ __align__(16) float As[GB_K][GB_M + 4];   // x tile, transposed
    __shared__ __align__(16) float Ws[GB_K][OUT_F];
    const int block_row = blockIdx.x * GB_M;
    const int tid = threadIdx.x;                   // 256 threads
    const int ty = tid >> 5;                       // warp id 0..7 -> rows ty*8..+7
    const int tx = tid & 31;                       // lane -> cols tx*4..+3
    const int lrow = tid >> 2;                     // 0..63
    const int lk4  = (tid & 3) * 4;                // 0,4,8,12

    unsigned long long acc2[4][4];
    #pragma unroll
    for (int i = 0; i < 4; i++)
        #pragma unroll
        for (int j = 0; j < 4; j++) acc2[i][j] = 0ULL;

    for (int k0 = 0; k0 < IN_F; k0 += GB_K) {
        float4 xv = make_float4(0.f, 0.f, 0.f, 0.f);
        int grow = block_row + lrow;
        if (grow < N_NODES)
            xv = *(const float4*)(x + (size_t)grow * IN_F + k0 + lk4);
        As[lk4 + 0][lrow] = xv.x;
        As[lk4 + 1][lrow] = xv.y;
        As[lk4 + 2][lrow] = xv.z;
        As[lk4 + 3][lrow] = xv.w;
        #pragma unroll
        for (int i = 0; i < 2; i++) {
            int fi = tid + i * 256;
            int wk = fi >> 5;
            int wn = (fi & 31) * 4;
            *(float4*)&Ws[wk][wn] =
                *(const float4*)(W + (size_t)(k0 + wk) * OUT_F + wn);
        }
        __syncthreads();
        #pragma unroll
        for (int k = 0; k < GB_K; k++) {
            float4 rnv = *(const float4*)&Ws[k][tx * 4];
            unsigned long long rnd[4] = {
                pack2(rnv.x, rnv.x), pack2(rnv.y, rnv.y),
                pack2(rnv.z, rnv.z), pack2(rnv.w, rnv.w)
            };
            #pragma unroll
            for (int i = 0; i < 4; i++) {
                unsigned long long rm =
                    *(const unsigned long long*)&As[k][ty * 8 + 2 * i];
                #pragma unroll
                for (int j = 0; j < 4; j++)
                    acc2[i][j] = fma2(rm, rnd[j], acc2[i][j]);
            }
        }
        __syncthreads();
    }

    float accf[8][4];
    #pragma unroll
    for (int i = 0; i < 4; i++)
        #pragma unroll
        for (int j = 0; j < 4; j++)
            unpack2(acc2[i][j], accf[2 * i][j], accf[2 * i + 1][j]);

    float4 as4 = ((const float4*)a)[tx];
    float4 ad4 = ((const float4*)(a + OUT_F))[tx];
    #pragma unroll
    for (int r = 0; r < 8; r++) {
        int grow = block_row + ty * 8 + r;
        if (grow < N_NODES) {
            float4 v = make_float4(accf[r][0], accf[r][1], accf[r][2], accf[r][3]);
            // fp16 payload store (uint2 = 4 halves)
            __half2 p0 = __floats2half2_rn(v.x, v.y);
            __half2 p1 = __floats2half2_rn(v.z, v.w);
            uint2 pk;
            pk.x = *(unsigned int*)&p0;
            pk.y = *(unsigned int*)&p1;
            ((uint2*)(g_hh + (size_t)grow * OUT_F))[tx] = pk;
            // fp32 score halves
            float s1 = v.x * as4.x + v.y * as4.y + v.z * as4.z + v.w * as4.w;
            float s2 = v.x * ad4.x + v.y * ad4.y + v.z * ad4.z + v.w * ad4.w;
            #pragma unroll
            for (int o = 16; o > 0; o >>= 1) {
                s1 += __shfl_xor_sync(0xFFFFFFFFu, s1, o);
                s2 += __shfl_xor_sync(0xFFFFFFFFu, s2, o);
            }
            if (tx == 0) {
                g_ssrc[grow] = s1;
                g_sdst[grow] = s2;
            }
        }
    }
}

// ---- aggregate: one warp per node; 4-edge unroll (MLP=4); fused div + ELU ------
__global__ __launch_bounds__(256) void aggregate_kernel(float* __restrict__ out) {
    int node = (blockIdx.x * blockDim.x + threadIdx.x) >> 5;
    int lane = threadIdx.x & 31;
    if (node >= N_NODES) return;

    int beg = g_rowptr[node];
    int deg = g_deg[node];
    int end = beg + deg;
    float ss = g_ssrc[node];

    float ax = 0.f, ay = 0.f, az = 0.f, aw = 0.f;
    float rowsum = 0.f;

    int e = beg;
    // 4-edge unrolled main loop: batch all index loads, then all row gathers,
    // then math — maximizes outstanding loads per warp.
    for (; e + 3 < end; e += 4) {
        int d0 = __ldg(&g_edst[e + 0]);
        int d1 = __ldg(&g_edst[e + 1]);
        int d2 = __ldg(&g_edst[e + 2]);
        int d3 = __ldg(&g_edst[e + 3]);
        uint2 r0 = __ldg(&((const uint2*)(g_hh + (size_t)d0 * OUT_F))[lane]);
        uint2 r1 = __ldg(&((const uint2*)(g_hh + (size_t)d1 * OUT_F))[lane]);
        uint2 r2 = __ldg(&((const uint2*)(g_hh + (size_t)d2 * OUT_F))[lane]);
        uint2 r3 = __ldg(&((const uint2*)(g_hh + (size_t)d3 * OUT_F))[lane]);
        float sc0 = ss + __ldg(&g_sdst[d0]);
        float sc1 = ss + __ldg(&g_sdst[d1]);
        float sc2 = ss + __ldg(&g_sdst[d2]);
        float sc3 = ss + __ldg(&g_sdst[d3]);
        float w0 = __expf(-(sc0 > 0.f ? sc0 : ALPHA * sc0));
        float w1 = __expf(-(sc1 > 0.f ? sc1 : ALPHA * sc1));
        float w2 = __expf(-(sc2 > 0.f ? sc2 : ALPHA * sc2));
        float w3 = __expf(-(sc3 > 0.f ? sc3 : ALPHA * sc3));
        rowsum += (w0 + w1) + (w2 + w3);
        float2 f00 = __half22float2(*(__half2*)&r0.x);
        float2 f01 = __half22float2(*(__half2*)&r0.y);
        float2 f10 = __half22float2(*(__half2*)&r1.x);
        float2 f11 = __half22float2(*(__half2*)&r1.y);
        float2 f20 = __half22float2(*(__half2*)&r2.x);
        float2 f21 = __half22float2(*(__half2*)&r2.y);
        float2 f30 = __half22float2(*(__half2*)&r3.x);
        float2 f31 = __half22float2(*(__half2*)&r3.y);
        ax += (w0 * f00.x + w1 * f10.x) + (w2 * f20.x + w3 * f30.x);
        ay += (w0 * f00.y + w1 * f10.y) + (w2 * f20.y + w3 * f30.y);
        az += (w0 * f01.x + w1 * f11.x) + (w2 * f21.x + w3 * f31.x);
        aw += (w0 * f01.y + w1 * f11.y) + (w2 * f21.y + w3 * f31.y);
    }
    for (; e < end; e++) {
        int d0 = __ldg(&g_edst[e]);
        uint2 r0 = __ldg(&((const uint2*)(g_hh + (size_t)d0 * OUT_F))[lane]);
        float sc0 = ss + __ldg(&g_sdst[d0]);
        float w0 = __expf(-(sc0 > 0.f ? sc0 : ALPHA * sc0));
        rowsum += w0;
        float2 f00 = __half22float2(*(__half2*)&r0.x);
        float2 f01 = __half22float2(*(__half2*)&r0.y);
        ax += w0 * f00.x;
        ay += w0 * f00.y;
        az += w0 * f01.x;
        aw += w0 * f01.y;
    }

    float inv = 1.0f / (rowsum + EPS_V);
    float hx = ax * inv, hy = ay * inv, hz = az * inv, hw = aw * inv;
    float4 r;
    r.x = hx > 0.f ? hx : (__expf(hx) - 1.0f);
    r.y = hy > 0.f ? hy : (__expf(hy) - 1.0f);
    r.z = hz > 0.f ? hz : (__expf(hz) - 1.0f);
    r.w = hw > 0.f ? hw : (__expf(hw) - 1.0f);
    ((float4*)(out + (size_t)node * OUT_F))[lane] = r;
}

// ---------------- launch --------------------------------------------------------
extern "C" void kernel_launch(void* const* d_in, const int* in_sizes, int n_in,
                              void* d_out, int out_size) {
    const float* x  = (const float*)d_in[0];
    const void*  ei = d_in[1];
    const float* W  = (const float*)d_in[2];
    const float* a  = (const float*)d_in[3];
    float* out = (float*)d_out;

    zero_counts_kernel<<<256, 256>>>();
    hist_kernel<<<2048, 256>>>(ei);
    deg_chunk_sum_kernel<<<NCHUNK, 256>>>();
    scan_chunk_sums_kernel<<<1, 256>>>();
    rowptr_kernel<<<NCHUNK, 256>>>();

    gemm_fill_kernel<<<GEMM_BLOCKS + FILL_BLOCKS, 256>>>(x, W, a, ei);

    int agg_blocks = (N_NODES * 32 + 255) / 256;          // 6250
    aggregate_kernel<<<agg_blocks, 256>>>(out);
}